// round 1
// baseline (speedup 1.0000x reference)
#include <cuda_runtime.h>

// WavUnPacking: inverse Haar DWT (db1, per-2x2 butterfly + interleave).
// x: (B=8, C=256, H=128, W=128) fp32 -> out: (B=8, C4=64, 2H=256, 2W=256) fp32
//
// Pure bandwidth kernel. Each thread handles 4 consecutive w positions via
// float4: 4x LDG.128 (ll/lh/hl/hh), 4x STG.128 (two output rows, interleaved
// even/odd columns). Fully coalesced on both sides.

static constexpr int B  = 8;
static constexpr int C4 = 64;     // output channels
static constexpr int H  = 128;
static constexpr int W4 = 128 / 4; // float4s per input row = 32

__global__ void __launch_bounds__(256)
wav_unpack_kernel(const float4* __restrict__ x, float4* __restrict__ out)
{
    int idx = blockIdx.x * blockDim.x + threadIdx.x;
    // idx layout: [b (8)][c (64)][h (128)][w4 (32)]
    int w4 = idx & (W4 - 1);          // 0..31
    int h  = (idx >> 5) & (H - 1);    // 0..127
    int bc = idx >> 12;               // b*64 + c, 0..511
    int b  = bc >> 6;
    int c  = bc & (C4 - 1);

    // input float4 index: channel = b*256 + c + k*64; per-channel plane = H*W4 f4
    const int plane = H * W4;                 // 128*32 = 4096 float4 per channel
    int base = ((b * 256 + c) * H + h) * W4 + w4;
    const int cs = C4 * plane;                // channel-group stride = 64 planes

    float4 ll = x[base];
    float4 lh = x[base + cs];
    float4 hl = x[base + 2 * cs];
    float4 hh = x[base + 3 * cs];

    // butterfly, *0.5
    float4 e00, e01, e10, e11;
    {
        float a, bb, cc, d;
        // lane x
        a = ll.x; bb = lh.x; cc = hl.x; d = hh.x;
        e00.x = 0.5f*(a+bb+cc+d); e01.x = 0.5f*(a+bb-cc-d);
        e10.x = 0.5f*(a-bb+cc-d); e11.x = 0.5f*(a-bb-cc+d);
        // lane y
        a = ll.y; bb = lh.y; cc = hl.y; d = hh.y;
        e00.y = 0.5f*(a+bb+cc+d); e01.y = 0.5f*(a+bb-cc-d);
        e10.y = 0.5f*(a-bb+cc-d); e11.y = 0.5f*(a-bb-cc+d);
        // lane z
        a = ll.z; bb = lh.z; cc = hl.z; d = hh.z;
        e00.z = 0.5f*(a+bb+cc+d); e01.z = 0.5f*(a+bb-cc-d);
        e10.z = 0.5f*(a-bb+cc-d); e11.z = 0.5f*(a-bb-cc+d);
        // lane w
        a = ll.w; bb = lh.w; cc = hl.w; d = hh.w;
        e00.w = 0.5f*(a+bb+cc+d); e01.w = 0.5f*(a+bb-cc-d);
        e10.w = 0.5f*(a-bb+cc-d); e11.w = 0.5f*(a-bb-cc+d);
    }

    // output: (bc) plane of 256x256 floats = 256 rows * 64 float4/row.
    // top row = 2h, bottom row = 2h+1. Each input w maps to output cols 2w,2w+1.
    // 4 input w's -> 8 output floats -> 2 float4 per row.
    int otop = (bc * 256 + 2 * h) * 64 + 2 * w4;
    out[otop]      = make_float4(e00.x, e01.x, e00.y, e01.y);
    out[otop + 1]  = make_float4(e00.z, e01.z, e00.w, e01.w);
    out[otop + 64] = make_float4(e10.x, e11.x, e10.y, e11.y);
    out[otop + 65] = make_float4(e10.z, e11.z, e10.w, e11.w);
}

extern "C" void kernel_launch(void* const* d_in, const int* in_sizes, int n_in,
                              void* d_out, int out_size)
{
    const float4* x = (const float4*)d_in[0];
    float4* out = (float4*)d_out;

    int total_threads = B * C4 * H * W4; // 8*64*128*32 = 2,097,152
    int block = 256;
    int grid = total_threads / block;    // 8192
    wav_unpack_kernel<<<grid, block>>>(x, out);
}